// round 4
// baseline (speedup 1.0000x reference)
#include <cuda_runtime.h>

#define BB     16
#define CC     3
#define HH     512
#define WW     512
#define NH     63
#define NW     63
#define NN     (NH * NW)          // 3969
#define FDIM   768
#define KNB    8
#define F4PER  192                // float4 per patch

#define BN_TOTAL      (BB * NN)                     // 63,504
#define BN_PER_BLOCK  8
#define PATCH_BLOCKS  (BN_TOTAL / BN_PER_BLOCK)     // 7,938 (exact)
#define TPB           192

#define POS_FLOATS    (BB * NN * 2)                 // 127,008
#define EDGE_FLOATS   (BB * 2 * NN * KNB)           // 1,016,064
#define EXTRA_FLOATS  (POS_FLOATS + EDGE_FLOATS)    // 1,143,072
#define EXTRA_BLOCKS  ((EXTRA_FLOATS + TPB - 1) / TPB)  // 5,954

#define CX(a, b) { int _lo = min(a, b); b = max(a, b); a = _lo; }

// ---------------------------------------------------------------------------
// One fused kernel, 192-thread blocks.
//
//  blocks [0, EXTRA_BLOCKS): positions + edge_index, one float per thread.
//    Edge targets recompute their own kNN in registers (sorted insertion
//    network over the Chebyshev radius-2 window; key = d2*4096 + idx
//    reproduces top_k(-d2)'s (d2 asc, idx asc) ordering).
//
//  blocks [EXTRA_BLOCKS, ...): patch gather. r = threadIdx.x is the
//    within-patch float4 index (c,u,vg hoisted out of the loop); the thread
//    walks 8 consecutive (b,n) patches with incremental (b,i,j) advance.
//    8 independent LDG.128 in flight, ~4 ALU ops per load.
// ---------------------------------------------------------------------------
__global__ void __launch_bounds__(TPB)
fused_kernel(const float* __restrict__ x, float* __restrict__ out)
{
    int bid = blockIdx.x;

    if (bid < EXTRA_BLOCKS) {
        int e = bid * TPB + threadIdx.x;
        if (e >= EXTRA_FLOATS) return;

        const long long P0 = (long long)BN_TOTAL * FDIM;

        if (e < POS_FLOATS) {
            int n = (e >> 1) % NN;
            out[P0 + e] = (float)((e & 1) ? (n % NW) : (n / NW));
            return;
        }

        int e2 = e - POS_FLOATS;
        int r  = e2 % (2 * NN * KNB);
        float v;
        if (r < NN * KNB) {
            v = (float)(r >> 3);                    // src row: node id
        } else {
            int q = r - NN * KNB;
            int n = q >> 3;
            int m = q & 7;
            int i = n / NW;
            int j = n % NW;

            int t0 = 0x7fffffff, t1 = 0x7fffffff, t2 = 0x7fffffff, t3 = 0x7fffffff;
            int t4 = 0x7fffffff, t5 = 0x7fffffff, t6 = 0x7fffffff, t7 = 0x7fffffff;
            #pragma unroll
            for (int di = -2; di <= 2; di++) {
                #pragma unroll
                for (int dj = -2; dj <= 2; dj++) {
                    if (di == 0 && dj == 0) continue;
                    int ii = i + di;
                    int jj = j + dj;
                    bool ok = (ii >= 0) & (ii < NH) & (jj >= 0) & (jj < NW);
                    int key = ok ? ((di*di + dj*dj) * 4096 + (ii * NW + jj))
                                 : 0x7fffffff;
                    int t8 = key;
                    CX(t7, t8); CX(t6, t7); CX(t5, t6); CX(t4, t5);
                    CX(t3, t4); CX(t2, t3); CX(t1, t2); CX(t0, t1);
                }
            }
            int a0 = (m & 1) ? t1 : t0;
            int a1 = (m & 1) ? t3 : t2;
            int a2 = (m & 1) ? t5 : t4;
            int a3 = (m & 1) ? t7 : t6;
            int b0 = (m & 2) ? a1 : a0;
            int b1 = (m & 2) ? a3 : a2;
            int sel = (m & 4) ? b1 : b0;
            v = (float)(sel & 4095);
        }
        out[P0 + POS_FLOATS + e2] = v;
        return;
    }

    // ---- patch gather ----
    int r  = threadIdx.x;               // 0..191, within-patch float4 index
    int c  = r >> 6;
    int u  = (r >> 2) & 15;
    int vg = r & 3;
    int off_in = (c * HH + u) * WW + vg * 4;   // float offset within x[b] plane set

    int bn0 = (bid - EXTRA_BLOCKS) * BN_PER_BLOCK;
    int b = bn0 / NN;
    int n = bn0 % NN;
    int i = n / NW;
    int j = n % NW;

    float4 val[BN_PER_BLOCK];
    #pragma unroll
    for (int k = 0; k < BN_PER_BLOCK; k++) {
        const float4* src = reinterpret_cast<const float4*>(
            x + ((long long)b * (CC * HH * WW) + i * (8 * WW) + j * 8 + off_in));
        val[k] = __ldg(src);
        // advance to next patch
        j++;
        if (j == NW) { j = 0; i++; }
        if (i == NH) { i = 0; b++; }
    }

    float4* dst = reinterpret_cast<float4*>(out) + (long long)bn0 * F4PER + r;
    #pragma unroll
    for (int k = 0; k < BN_PER_BLOCK; k++)
        __stcs(dst + (long long)k * F4PER, val[k]);
}

// ---------------------------------------------------------------------------
extern "C" void kernel_launch(void* const* d_in, const int* in_sizes, int n_in,
                              void* d_out, int out_size)
{
    const float* x = (const float*)d_in[0];
    float* out = (float*)d_out;

    fused_kernel<<<EXTRA_BLOCKS + PATCH_BLOCKS, TPB>>>(x, out);
}